// round 14
// baseline (speedup 1.0000x reference)
#include <cuda_runtime.h>
#include <cstdint>
#include <math.h>

#define B_     4
#define NCH    32
#define T_FULL 65536
#define T_IN   8192
#define L_     256
#define HOP_   256
#define H_     64
#define KC_    24576

// ---- scratch (device globals; no allocation allowed) ----
__device__ float g_H [B_*NCH*T_FULL];   // hidden state buffer A
__device__ float g_C [B_*NCH*T_FULL];   // hidden state buffer B (double-buffer)
__device__ float g_F0[B_*H_*L_];
__device__ float g_KT[B_*L_*KC_];       // predicted kernels [n=b*L+l][kc]
__device__ float g_BS[B_*256*L_];       // predicted biases [b][bc][l]

__device__ __forceinline__ float lrelu(float x){ return x >= 0.f ? x : 0.2f*x; }

// ---- packed f32x2 helpers ----
__device__ __forceinline__ uint64_t pack2f(float lo, float hi){
    uint64_t r; asm("mov.b64 %0, {%1, %2};" : "=l"(r) : "f"(lo), "f"(hi)); return r;
}
__device__ __forceinline__ uint64_t bcast2f(float x){ return pack2f(x, x); }
__device__ __forceinline__ void fma2(uint64_t& d, uint64_t a, uint64_t b){
    asm("fma.rn.f32x2 %0, %1, %2, %0;" : "+l"(d) : "l"(a), "l"(b));
}
__device__ __forceinline__ float2 unpack2f(uint64_t v){
    float2 r; asm("mov.b64 {%0, %1}, %2;" : "=f"(r.x), "=f"(r.y) : "l"(v)); return r;
}

// ============================================================
// K1: conv_transpose1d  (stride 8, K=16, pad 4) -> g_H
// ============================================================
__global__ void k_convT(const float* __restrict__ x, const float* __restrict__ w,
                        const float* __restrict__ bias){
    int b  = blockIdx.y;
    int t0 = blockIdx.x * 256;
    int tid = threadIdx.x;
    int r = tid & 7, o = tid >> 3;
    __shared__ float xs[NCH*36];
    const float* xb = x + b*NCH*T_IN;
    int jbase = t0/8 - 1;
    for (int idx = tid; idx < NCH*34; idx += 256){
        int c = idx / 34, p = idx % 34;
        int j = jbase + p;
        xs[c*36 + p] = (j >= 0 && j < T_IN) ? xb[c*T_IN + j] : 0.f;
    }
    __syncthreads();
    float acc[32];
    float bv = bias[o];
    #pragma unroll
    for (int s = 0; s < 32; s++) acc[s] = bv;
    int off = (r + 4) & 7;
    int e   = (off >= 4) ? 1 : 0;
    for (int i = 0; i < NCH; i++){
        float w1 = w[(i*32 + o)*16 + r];
        float w2 = w[(i*32 + o)*16 + r + 8];
        const float* xr = &xs[i*36 + e];
        float vp = xr[0];
        #pragma unroll
        for (int s = 0; s < 32; s++){
            float v = xr[s + 1];
            acc[s] += w1*v + w2*vp;
            vp = v;
        }
    }
    float* out = &g_H[(b*NCH + o)*T_FULL];
    #pragma unroll
    for (int s = 0; s < 32; s++) out[t0 + off + 8*s] = acc[s];
}

// ============================================================
// K2: FUSED kernel predictor (spec conv + 3 residual blocks).
// ============================================================
#define PRED_SMEM ((100*52 + 64*52 + 64*52 + 16000)*4)

__device__ __forceinline__ void pred_conv3(
    const float* src, float* dst, const float* rsd, float* wbuf,
    const float* __restrict__ wsrc, const float* __restrict__ bsrc,
    int plo, int phi, int l0, int hq, int pb, int tid){
    __syncthreads();
    for (int idx = tid; idx < 64*192; idx += 256){
        int h = idx/192, ck = idx%192;
        wbuf[ck*64 + h] = wsrc[h*192 + ck];
    }
    __syncthreads();
    uint64_t acc[2][3];
    #pragma unroll
    for (int m = 0; m < 2; m++){
        uint64_t bp = pack2f(bsrc[hq*4 + 2*m], bsrc[hq*4 + 2*m + 1]);
        acc[m][0]=bp; acc[m][1]=bp; acc[m][2]=bp;
    }
    for (int c = 0; c < 64; c++){
        float xv[5];
        #pragma unroll
        for (int m = 0; m < 5; m++) xv[m] = src[c*52 + pb + 1 + m];
        #pragma unroll
        for (int k = 0; k < 3; k++){
            ulonglong2 wp = *(const ulonglong2*)&wbuf[(c*3 + k)*64 + hq*4];
            #pragma unroll
            for (int j = 0; j < 3; j++){
                uint64_t xb = bcast2f(xv[j + k]);
                fma2(acc[0][j], wp.x, xb);
                fma2(acc[1][j], wp.y, xb);
            }
        }
    }
    #pragma unroll
    for (int m = 0; m < 2; m++)
    #pragma unroll
    for (int j = 0; j < 3; j++){
        int p = pb + j;
        if (p >= plo && p <= phi){
            int gl = l0 - 8 + p;
            bool ok = (gl >= 0 && gl < L_);
            float2 u = unpack2f(acc[m][j]);
            int ch0 = hq*4 + 2*m;
            float v0 = lrelu(u.x), v1 = lrelu(u.y);
            if (rsd){ v0 += rsd[ch0*52 + p + 2]; v1 += rsd[(ch0+1)*52 + p + 2]; }
            dst[ch0*52 + p + 2]     = ok ? v0 : 0.f;
            dst[(ch0+1)*52 + p + 2] = ok ? v1 : 0.f;
        }
    }
}

__global__ void __launch_bounds__(256)
k_pred(const float* __restrict__ spec,
       const float* __restrict__ kp_w, const float* __restrict__ kp_b,
       const float* __restrict__ rb_w1, const float* __restrict__ rb_b1,
       const float* __restrict__ rb_w2, const float* __restrict__ rb_b2){
    extern __shared__ float sm[];
    float* sspec = sm;
    float* bufA  = sm + 100*52;
    float* bufB  = bufA + 64*52;
    float* wbuf  = bufB + 64*52;
    int b = blockIdx.x, ls = blockIdx.y;
    int l0 = ls*32;
    int tid = threadIdx.x;
    int hq = tid >> 4;
    int pb = (tid & 15) * 3;

    const float* sp = spec + b*100*L_;
    for (int idx = tid; idx < 100*52; idx += 256){
        int c = idx/52, q = idx%52;
        int gl = l0 - 10 + q;
        sspec[c*52 + q] = (gl >= 0 && gl < L_) ? sp[c*L_ + gl] : 0.f;
    }
    uint64_t acc[2][3];
    #pragma unroll
    for (int m = 0; m < 2; m++){
        uint64_t bp = pack2f(kp_b[hq*4 + 2*m], kp_b[hq*4 + 2*m + 1]);
        acc[m][0]=bp; acc[m][1]=bp; acc[m][2]=bp;
    }
    for (int chunk = 0; chunk < 2; chunk++){
        __syncthreads();
        for (int idx = tid; idx < 16000; idx += 256){
            int h = idx/250, ck = idx%250;
            wbuf[ck*64 + h] = kp_w[h*500 + chunk*250 + ck];
        }
        __syncthreads();
        for (int c2 = 0; c2 < 50; c2++){
            int c = chunk*50 + c2;
            float xv[7];
            #pragma unroll
            for (int m = 0; m < 7; m++) xv[m] = sspec[c*52 + pb + m];
            #pragma unroll
            for (int k = 0; k < 5; k++){
                ulonglong2 wp = *(const ulonglong2*)&wbuf[(c2*5 + k)*64 + hq*4];
                #pragma unroll
                for (int j = 0; j < 3; j++){
                    uint64_t xb = bcast2f(xv[j + k]);
                    fma2(acc[0][j], wp.x, xb);
                    fma2(acc[1][j], wp.y, xb);
                }
            }
        }
    }
    #pragma unroll
    for (int m = 0; m < 2; m++)
    #pragma unroll
    for (int j = 0; j < 3; j++){
        int p = pb + j;
        if (p >= 2 && p <= 45){
            int gl = l0 - 8 + p;
            bool ok = (gl >= 0 && gl < L_);
            float2 u = unpack2f(acc[m][j]);
            int ch0 = hq*4 + 2*m;
            bufA[ch0*52 + p + 2]     = ok ? u.x : 0.f;
            bufA[(ch0+1)*52 + p + 2] = ok ? u.y : 0.f;
        }
    }
    #pragma unroll 1
    for (int i = 0; i < 3; i++){
        pred_conv3(bufA, bufB, nullptr, wbuf, rb_w1 + i*12288, rb_b1 + i*64,
                   3+2*i, 44-2*i, l0, hq, pb, tid);
        pred_conv3(bufB, bufA, bufA,    wbuf, rb_w2 + i*12288, rb_b2 + i*64,
                   4+2*i, 43-2*i, l0, hq, pb, tid);
    }
    __syncthreads();
    #pragma unroll
    for (int m = 0; m < 2; m++)
    #pragma unroll
    for (int j = 0; j < 3; j++){
        int p = pb + j;
        if (p >= 8 && p <= 39){
            int l = l0 - 8 + p;
            int ch0 = hq*4 + 2*m;
            g_F0[(b*H_ + ch0    )*L_ + l] = bufA[ch0*52 + p + 2];
            g_F0[(b*H_ + ch0 + 1)*L_ + l] = bufA[(ch0+1)*52 + p + 2];
        }
    }
}

// ============================================================
// K5: kern conv GEMM (f32x2), tile 128(kc) x 64(n), double-
// buffered; X staged as PRE-DUPLICATED (x,x) pairs in a
// contiguous layout (no broadcast MOVs in inner loop).
// 2 tail block-rows compute the bias conv into g_BS.
// ============================================================
__global__ void __launch_bounds__(256)
k_kern_gemm(const float* __restrict__ A, const float* __restrict__ Ab,
            const float* __restrict__ Bw, const float* __restrict__ Bb){
    int kc0 = blockIdx.x * 128;
    bool is_bias = (kc0 >= KC_);
    int n0  = blockIdx.y * 64;
    int b   = n0 / L_;
    int l0w = n0 % L_;
    int tid = threadIdx.x;
    int warp = tid >> 5, lane = tid & 31;
    int ty = (warp << 1) | (lane >> 4);
    int tx = lane & 15;
    __shared__ __align__(16) float As[2][16][128];
    __shared__ __align__(16) float Xs2[2][16][136];   // (x,x) pairs: [kk][tx*8+2q]
    const float* F = &g_F0[b*H_*L_];
    const float* Arow_base = is_bias ? Bw : A;
    const float* bias_base = is_bias ? Bb : Ab;
    int row_off = is_bias ? (kc0 - KC_) : kc0;

    uint64_t acc[4][4];
    #pragma unroll
    for (int m = 0; m < 4; m++){
        uint64_t bp = pack2f(bias_base[row_off + ty*8 + 2*m],
                             bias_base[row_off + ty*8 + 2*m + 1]);
        #pragma unroll
        for (int j = 0; j < 4; j++) acc[m][j] = bp;
    }
    int arow = tid >> 1, ac0 = (tid & 1) * 8;
    int xrr = tid >> 4, xg = tid & 15;
    const float* Aptr = &Arow_base[(row_off + arow)*192 + ac0];

    // prologue: stage bk=0 into buffer 0
    {
        float4 v0 = *(const float4*)(Aptr);
        float4 v1 = *(const float4*)(Aptr + 4);
        As[0][ac0+0][arow] = v0.x; As[0][ac0+1][arow] = v0.y;
        As[0][ac0+2][arow] = v0.z; As[0][ac0+3][arow] = v0.w;
        As[0][ac0+4][arow] = v1.x; As[0][ac0+5][arow] = v1.y;
        As[0][ac0+6][arow] = v1.z; As[0][ac0+7][arow] = v1.w;
        int hh = xrr/3, k = xrr%3;
        #pragma unroll
        for (int q = 0; q < 4; q++){
            int t = l0w + xg*4 + q + k - 1;
            float v = (t >= 0 && t < L_) ? F[hh*L_ + t] : 0.f;
            *(uint64_t*)&Xs2[0][xrr][xg*8 + 2*q] = bcast2f(v);
        }
    }
    __syncthreads();

    #pragma unroll 1
    for (int bk = 0; bk < 12; bk++){
        int cur = bk & 1, nxt = cur ^ 1;
        if (bk < 11){
            int r0 = (bk + 1)*16;
            float4 v0 = *(const float4*)(Aptr + r0);
            float4 v1 = *(const float4*)(Aptr + r0 + 4);
            As[nxt][ac0+0][arow] = v0.x; As[nxt][ac0+1][arow] = v0.y;
            As[nxt][ac0+2][arow] = v0.z; As[nxt][ac0+3][arow] = v0.w;
            As[nxt][ac0+4][arow] = v1.x; As[nxt][ac0+5][arow] = v1.y;
            As[nxt][ac0+6][arow] = v1.z; As[nxt][ac0+7][arow] = v1.w;
            int r = r0 + xrr;
            int hh = r/3, k = r%3;
            #pragma unroll
            for (int q = 0; q < 4; q++){
                int t = l0w + xg*4 + q + k - 1;
                float v = (t >= 0 && t < L_) ? F[hh*L_ + t] : 0.f;
                *(uint64_t*)&Xs2[nxt][xrr][xg*8 + 2*q] = bcast2f(v);
            }
        }
        #pragma unroll
        for (int kk = 0; kk < 16; kk++){
            ulonglong2 aA = *(const ulonglong2*)&As[cur][kk][ty*8];
            ulonglong2 aB = *(const ulonglong2*)&As[cur][kk][ty*8 + 4];
            uint64_t a2[4] = {aA.x, aA.y, aB.x, aB.y};
            ulonglong2 xA = *(const ulonglong2*)&Xs2[cur][kk][tx*8];
            ulonglong2 xB = *(const ulonglong2*)&Xs2[cur][kk][tx*8 + 4];
            uint64_t xb[4] = {xA.x, xA.y, xB.x, xB.y};
            #pragma unroll
            for (int j = 0; j < 4; j++)
                #pragma unroll
                for (int m = 0; m < 4; m++)
                    fma2(acc[m][j], a2[m], xb[j]);
        }
        __syncthreads();
    }
    if (!is_bias){
        #pragma unroll
        for (int j = 0; j < 4; j++){
            int n = n0 + tx*4 + j;
            #pragma unroll
            for (int m = 0; m < 4; m++){
                float2 p = unpack2f(acc[m][j]);
                *(float2*)&g_KT[n*KC_ + kc0 + ty*8 + 2*m] = p;
            }
        }
    } else {
        #pragma unroll
        for (int j = 0; j < 4; j++){
            int l = l0w + tx*4 + j;
            #pragma unroll
            for (int m = 0; m < 4; m++){
                float2 p = unpack2f(acc[m][j]);
                int bc = row_off + ty*8 + 2*m;
                g_BS[(b*256 + bc    )*L_ + l] = p.x;
                g_BS[(b*256 + bc + 1)*L_ + l] = p.y;
            }
        }
    }
}

// ============================================================
// K7+K8 FUSED: lrelu -> dilated conv -> lrelu (smem sc)
// -> LVC + bias + gating + residual.
// INTERLEAVED sample mapping (samples = base + lane + 32m):
// all scalar smem accesses are lane-contiguous (conflict-free).
// Thread covers 8 channels x 4 samples.
// ============================================================
#define FUSED_SMEM ((32*312 + 3072 + 32*264 + 6144)*4)
template<int D>
__global__ void __launch_bounds__(256)
k_fused(int layer, const float* __restrict__ w, const float* __restrict__ bias,
        float* __restrict__ outp){
    extern __shared__ float sm[];
    float* sx  = sm;                    // 32 x 312: lrelu(Hin) window
    float* ws  = sm + 32*312;           // [k][i][o] 3072
    float* sc  = ws + 3072;             // 32 x 264 (258 used): conv out
    float* ksh = sc + 32*264;           // [k][c][o] 6144
    int b = blockIdx.y, l = blockIdx.x;
    int tid = threadIdx.x;
    int lane = tid & 31, warp = tid >> 5;
    int tseg = l*HOP_;
    const float* Hin  = (layer & 1) ? g_C : g_H;
    float* Hout = outp ? outp : ((layer & 1) ? g_H : g_C);
    const float* Hb = &Hin[b*NCH*T_FULL];

    const int W2 = 258 + 2*D;
    for (int idx = tid; idx < NCH*W2; idx += 256){
        int c = idx / W2, q = idx % W2;
        int t = tseg - 1 - D + q;
        sx[c*312 + q] = (t >= 0 && t < T_FULL) ? lrelu(Hb[c*T_FULL + t]) : 0.f;
    }
    for (int idx = tid; idx < 3072; idx += 256){
        int o = idx / 96, rem = idx % 96;
        int i = rem / 3, k = rem % 3;
        ws[k*1024 + i*32 + o] = w[idx];
    }
    const float* KTb = &g_KT[(b*L_ + l)*KC_ + layer*6144];
    const float4* K4 = (const float4*)KTb;
    for (int i4 = tid; i4 < 1536; i4 += 256){
        float4 v = K4[i4];
        float vv[4] = {v.x, v.y, v.z, v.w};
        int base = i4*4;
        #pragma unroll
        for (int e = 0; e < 4; e++){
            int idx = base + e;
            int c = idx / 192, rem = idx % 192;
            int o = rem / 3, k = rem % 3;
            ksh[k*2048 + c*64 + o] = vv[e];
        }
    }
    __syncthreads();

    int o0    = (warp & 3) * 8;            // 8 channels per thread
    int sbase = (warp >> 2) * 128 + lane;  // samples sbase + 32m, m=0..3

    // --- dconv phase 1: p in [0,256) via interleaved mapping ---
    {
        uint64_t acc[4][4];                // [ch pair][m]
        #pragma unroll
        for (int cp = 0; cp < 4; cp++){
            uint64_t bp = pack2f(bias[o0 + 2*cp], bias[o0 + 2*cp + 1]);
            #pragma unroll
            for (int m = 0; m < 4; m++) acc[cp][m] = bp;
        }
        for (int i = 0; i < NCH; i++){
            const float* xr = &sx[i*312 + sbase];
            #pragma unroll
            for (int k = 0; k < 3; k++){
                ulonglong2 wA = *(const ulonglong2*)&ws[k*1024 + i*32 + o0];
                ulonglong2 wB = *(const ulonglong2*)&ws[k*1024 + i*32 + o0 + 4];
                uint64_t wp[4] = {wA.x, wA.y, wB.x, wB.y};
                #pragma unroll
                for (int m = 0; m < 4; m++){
                    uint64_t xb = bcast2f(xr[32*m + k*D]);
                    fma2(acc[0][m], wp[0], xb);
                    fma2(acc[1][m], wp[1], xb);
                    fma2(acc[2][m], wp[2], xb);
                    fma2(acc[3][m], wp[3], xb);
                }
            }
        }
        #pragma unroll
        for (int cp = 0; cp < 4; cp++)
            #pragma unroll
            for (int m = 0; m < 4; m++){
                float2 u = unpack2f(acc[cp][m]);
                int p = sbase + 32*m;
                float v0 = lrelu(u.x), v1 = lrelu(u.y);
                if (l == 0 && p == 0){ v0 = 0.f; v1 = 0.f; }   // LVC zero-pad t=-1
                sc[(o0 + 2*cp    )*264 + p] = v0;
                sc[(o0 + 2*cp + 1)*264 + p] = v1;
            }
    }
    // --- dconv phase 2: p = 256, 257 (64 values, scalar, warps 0-1) ---
    if (tid < 64){
        int ch = tid >> 1, p = 256 + (tid & 1);
        float acc = bias[ch];
        for (int i = 0; i < NCH; i++){
            #pragma unroll
            for (int k = 0; k < 3; k++)
                acc += ws[k*1024 + i*32 + ch] * sx[i*312 + p + k*D];
        }
        float v = lrelu(acc);
        if (l == L_ - 1 && p == 257) v = 0.f;         // LVC zero-pad t=T
        sc[ch*264 + p] = v;
    }
    __syncthreads();

    // --- LVC + gate + residual: 8 ch x 4 interleaved samples ---
    const float* Bb = &g_BS[(b*256 + layer*64)*L_];
    uint64_t accL[4][4], accH[4][4];
    #pragma unroll
    for (int cp = 0; cp < 4; cp++){
        uint64_t bl = pack2f(Bb[(o0 + 2*cp     )*L_ + l], Bb[(o0 + 2*cp + 1 )*L_ + l]);
        uint64_t bh = pack2f(Bb[(o0 + 2*cp + 32)*L_ + l], Bb[(o0 + 2*cp + 33)*L_ + l]);
        #pragma unroll
        for (int m = 0; m < 4; m++){ accL[cp][m] = bl; accH[cp][m] = bh; }
    }
    for (int c = 0; c < NCH; c++){
        const float* xr = &sc[c*264 + sbase];
        #pragma unroll
        for (int k = 0; k < 3; k++){
            ulonglong2 wlA = *(const ulonglong2*)&ksh[k*2048 + c*64 + o0];
            ulonglong2 wlB = *(const ulonglong2*)&ksh[k*2048 + c*64 + o0 + 4];
            ulonglong2 whA = *(const ulonglong2*)&ksh[k*2048 + c*64 + o0 + 32];
            ulonglong2 whB = *(const ulonglong2*)&ksh[k*2048 + c*64 + o0 + 36];
            uint64_t wl[4] = {wlA.x, wlA.y, wlB.x, wlB.y};
            uint64_t wh[4] = {whA.x, whA.y, whB.x, whB.y};
            #pragma unroll
            for (int m = 0; m < 4; m++){
                uint64_t xb = bcast2f(xr[32*m + k]);
                fma2(accL[0][m], wl[0], xb);
                fma2(accL[1][m], wl[1], xb);
                fma2(accL[2][m], wl[2], xb);
                fma2(accL[3][m], wl[3], xb);
                fma2(accH[0][m], wh[0], xb);
                fma2(accH[1][m], wh[1], xb);
                fma2(accH[2][m], wh[2], xb);
                fma2(accH[3][m], wh[3], xb);
            }
        }
    }
    #pragma unroll
    for (int cp = 0; cp < 4; cp++)
        #pragma unroll
        for (int m = 0; m < 4; m++){
            int s = sbase + 32*m;
            int oc0 = o0 + 2*cp;
            float2 uL = unpack2f(accL[cp][m]);
            float2 uH = unpack2f(accH[cp][m]);
            float r0 = Hb[(oc0    )*T_FULL + tseg + s];
            float r1 = Hb[(oc0 + 1)*T_FULL + tseg + s];
            float sg0 = 1.f / (1.f + __expf(-uL.x));
            float sg1 = 1.f / (1.f + __expf(-uL.y));
            float th0 = tanhf(uH.x);
            float th1 = tanhf(uH.y);
            Hout[(b*NCH + oc0    )*T_FULL + tseg + s] = sg0*th0 + r0;
            Hout[(b*NCH + oc0 + 1)*T_FULL + tseg + s] = sg1*th1 + r1;
        }
}

// ============================================================
extern "C" void kernel_launch(void* const* d_in, const int* in_sizes, int n_in,
                              void* d_out, int out_size){
    const float* hidden  = (const float*)d_in[0];
    const float* spec    = (const float*)d_in[1];
    const float* convt_w = (const float*)d_in[2];
    const float* convt_b = (const float*)d_in[3];
    const float* kp_in_w = (const float*)d_in[4];
    const float* kp_in_b = (const float*)d_in[5];
    const float* rb_w1   = (const float*)d_in[6];
    const float* rb_b1   = (const float*)d_in[7];
    const float* rb_w2   = (const float*)d_in[8];
    const float* rb_b2   = (const float*)d_in[9];
    const float* kern_w  = (const float*)d_in[10];
    const float* kern_b  = (const float*)d_in[11];
    const float* bias_w  = (const float*)d_in[12];
    const float* bias_b  = (const float*)d_in[13];
    const float* lvc_w   = (const float*)d_in[14];
    const float* lvc_b   = (const float*)d_in[15];

    cudaFuncSetAttribute(k_pred, cudaFuncAttributeMaxDynamicSharedMemorySize, PRED_SMEM);
    cudaFuncSetAttribute(k_fused<1>,  cudaFuncAttributeMaxDynamicSharedMemorySize, FUSED_SMEM);
    cudaFuncSetAttribute(k_fused<3>,  cudaFuncAttributeMaxDynamicSharedMemorySize, FUSED_SMEM);
    cudaFuncSetAttribute(k_fused<9>,  cudaFuncAttributeMaxDynamicSharedMemorySize, FUSED_SMEM);
    cudaFuncSetAttribute(k_fused<27>, cudaFuncAttributeMaxDynamicSharedMemorySize, FUSED_SMEM);

    k_convT<<<dim3(256, B_), 256>>>(hidden, convt_w, convt_b);
    k_pred<<<dim3(B_, 8), 256, PRED_SMEM>>>(spec, kp_in_w, kp_in_b,
                                            rb_w1, rb_b1, rb_w2, rb_b2);
    // GEMM + fused bias conv
    k_kern_gemm<<<dim3(KC_/128 + 2, (B_*L_)/64), 256>>>(kern_w, kern_b, bias_w, bias_b);

    // four fused dconv+LVC layers (first one lands at ncu position)
    dim3 dg(L_, B_);
    k_fused<1> <<<dg, 256, FUSED_SMEM>>>(0, lvc_w,        lvc_b,      nullptr);
    k_fused<3> <<<dg, 256, FUSED_SMEM>>>(1, lvc_w + 3072, lvc_b + 32, nullptr);
    k_fused<9> <<<dg, 256, FUSED_SMEM>>>(2, lvc_w + 6144, lvc_b + 64, nullptr);
    k_fused<27><<<dg, 256, FUSED_SMEM>>>(3, lvc_w + 9216, lvc_b + 96, (float*)d_out);
}

// round 16
// speedup vs baseline: 1.1244x; 1.1244x over previous
#include <cuda_runtime.h>
#include <cstdint>
#include <math.h>

#define B_     4
#define NCH    32
#define T_FULL 65536
#define T_IN   8192
#define L_     256
#define HOP_   256
#define H_     64
#define KC_    24576

// ---- scratch (device globals; no allocation allowed) ----
__device__ float g_H [B_*NCH*T_FULL];   // hidden state buffer A
__device__ float g_C [B_*NCH*T_FULL];   // hidden state buffer B (double-buffer)
__device__ float g_F0[B_*H_*L_];
__device__ float g_KT[B_*L_*KC_];       // predicted kernels [n=b*L+l][kc]
__device__ float g_BS[B_*256*L_];       // predicted biases [b][bc][l]

__device__ __forceinline__ float lrelu(float x){ return x >= 0.f ? x : 0.2f*x; }

// ---- packed f32x2 helpers ----
__device__ __forceinline__ uint64_t pack2f(float lo, float hi){
    uint64_t r; asm("mov.b64 %0, {%1, %2};" : "=l"(r) : "f"(lo), "f"(hi)); return r;
}
__device__ __forceinline__ uint64_t bcast2f(float x){ return pack2f(x, x); }
__device__ __forceinline__ void fma2(uint64_t& d, uint64_t a, uint64_t b){
    asm("fma.rn.f32x2 %0, %1, %2, %0;" : "+l"(d) : "l"(a), "l"(b));
}
__device__ __forceinline__ float2 unpack2f(uint64_t v){
    float2 r; asm("mov.b64 {%0, %1}, %2;" : "=f"(r.x), "=f"(r.y) : "l"(v)); return r;
}

// ============================================================
// K1: conv_transpose1d  (stride 8, K=16, pad 4) -> g_H
// ============================================================
__global__ void k_convT(const float* __restrict__ x, const float* __restrict__ w,
                        const float* __restrict__ bias){
    int b  = blockIdx.y;
    int t0 = blockIdx.x * 256;
    int tid = threadIdx.x;
    int r = tid & 7, o = tid >> 3;
    __shared__ float xs[NCH*36];
    const float* xb = x + b*NCH*T_IN;
    int jbase = t0/8 - 1;
    for (int idx = tid; idx < NCH*34; idx += 256){
        int c = idx / 34, p = idx % 34;
        int j = jbase + p;
        xs[c*36 + p] = (j >= 0 && j < T_IN) ? xb[c*T_IN + j] : 0.f;
    }
    __syncthreads();
    float acc[32];
    float bv = bias[o];
    #pragma unroll
    for (int s = 0; s < 32; s++) acc[s] = bv;
    int off = (r + 4) & 7;
    int e   = (off >= 4) ? 1 : 0;
    for (int i = 0; i < NCH; i++){
        float w1 = w[(i*32 + o)*16 + r];
        float w2 = w[(i*32 + o)*16 + r + 8];
        const float* xr = &xs[i*36 + e];
        float vp = xr[0];
        #pragma unroll
        for (int s = 0; s < 32; s++){
            float v = xr[s + 1];
            acc[s] += w1*v + w2*vp;
            vp = v;
        }
    }
    float* out = &g_H[(b*NCH + o)*T_FULL];
    #pragma unroll
    for (int s = 0; s < 32; s++) out[t0 + off + 8*s] = acc[s];
}

// ============================================================
// K2: FUSED kernel predictor (spec conv + 3 residual blocks).
// ============================================================
#define PRED_SMEM ((100*52 + 64*52 + 64*52 + 16000)*4)

__device__ __forceinline__ void pred_conv3(
    const float* src, float* dst, const float* rsd, float* wbuf,
    const float* __restrict__ wsrc, const float* __restrict__ bsrc,
    int plo, int phi, int l0, int hq, int pb, int tid){
    __syncthreads();
    for (int idx = tid; idx < 64*192; idx += 256){
        int h = idx/192, ck = idx%192;
        wbuf[ck*64 + h] = wsrc[h*192 + ck];
    }
    __syncthreads();
    uint64_t acc[2][3];
    #pragma unroll
    for (int m = 0; m < 2; m++){
        uint64_t bp = pack2f(bsrc[hq*4 + 2*m], bsrc[hq*4 + 2*m + 1]);
        acc[m][0]=bp; acc[m][1]=bp; acc[m][2]=bp;
    }
    for (int c = 0; c < 64; c++){
        float xv[5];
        #pragma unroll
        for (int m = 0; m < 5; m++) xv[m] = src[c*52 + pb + 1 + m];
        #pragma unroll
        for (int k = 0; k < 3; k++){
            ulonglong2 wp = *(const ulonglong2*)&wbuf[(c*3 + k)*64 + hq*4];
            #pragma unroll
            for (int j = 0; j < 3; j++){
                uint64_t xb = bcast2f(xv[j + k]);
                fma2(acc[0][j], wp.x, xb);
                fma2(acc[1][j], wp.y, xb);
            }
        }
    }
    #pragma unroll
    for (int m = 0; m < 2; m++)
    #pragma unroll
    for (int j = 0; j < 3; j++){
        int p = pb + j;
        if (p >= plo && p <= phi){
            int gl = l0 - 8 + p;
            bool ok = (gl >= 0 && gl < L_);
            float2 u = unpack2f(acc[m][j]);
            int ch0 = hq*4 + 2*m;
            float v0 = lrelu(u.x), v1 = lrelu(u.y);
            if (rsd){ v0 += rsd[ch0*52 + p + 2]; v1 += rsd[(ch0+1)*52 + p + 2]; }
            dst[ch0*52 + p + 2]     = ok ? v0 : 0.f;
            dst[(ch0+1)*52 + p + 2] = ok ? v1 : 0.f;
        }
    }
}

__global__ void __launch_bounds__(256)
k_pred(const float* __restrict__ spec,
       const float* __restrict__ kp_w, const float* __restrict__ kp_b,
       const float* __restrict__ rb_w1, const float* __restrict__ rb_b1,
       const float* __restrict__ rb_w2, const float* __restrict__ rb_b2){
    extern __shared__ float sm[];
    float* sspec = sm;
    float* bufA  = sm + 100*52;
    float* bufB  = bufA + 64*52;
    float* wbuf  = bufB + 64*52;
    int b = blockIdx.x, ls = blockIdx.y;
    int l0 = ls*32;
    int tid = threadIdx.x;
    int hq = tid >> 4;
    int pb = (tid & 15) * 3;

    const float* sp = spec + b*100*L_;
    for (int idx = tid; idx < 100*52; idx += 256){
        int c = idx/52, q = idx%52;
        int gl = l0 - 10 + q;
        sspec[c*52 + q] = (gl >= 0 && gl < L_) ? sp[c*L_ + gl] : 0.f;
    }
    uint64_t acc[2][3];
    #pragma unroll
    for (int m = 0; m < 2; m++){
        uint64_t bp = pack2f(kp_b[hq*4 + 2*m], kp_b[hq*4 + 2*m + 1]);
        acc[m][0]=bp; acc[m][1]=bp; acc[m][2]=bp;
    }
    for (int chunk = 0; chunk < 2; chunk++){
        __syncthreads();
        for (int idx = tid; idx < 16000; idx += 256){
            int h = idx/250, ck = idx%250;
            wbuf[ck*64 + h] = kp_w[h*500 + chunk*250 + ck];
        }
        __syncthreads();
        for (int c2 = 0; c2 < 50; c2++){
            int c = chunk*50 + c2;
            float xv[7];
            #pragma unroll
            for (int m = 0; m < 7; m++) xv[m] = sspec[c*52 + pb + m];
            #pragma unroll
            for (int k = 0; k < 5; k++){
                ulonglong2 wp = *(const ulonglong2*)&wbuf[(c2*5 + k)*64 + hq*4];
                #pragma unroll
                for (int j = 0; j < 3; j++){
                    uint64_t xb = bcast2f(xv[j + k]);
                    fma2(acc[0][j], wp.x, xb);
                    fma2(acc[1][j], wp.y, xb);
                }
            }
        }
    }
    #pragma unroll
    for (int m = 0; m < 2; m++)
    #pragma unroll
    for (int j = 0; j < 3; j++){
        int p = pb + j;
        if (p >= 2 && p <= 45){
            int gl = l0 - 8 + p;
            bool ok = (gl >= 0 && gl < L_);
            float2 u = unpack2f(acc[m][j]);
            int ch0 = hq*4 + 2*m;
            bufA[ch0*52 + p + 2]     = ok ? u.x : 0.f;
            bufA[(ch0+1)*52 + p + 2] = ok ? u.y : 0.f;
        }
    }
    #pragma unroll 1
    for (int i = 0; i < 3; i++){
        pred_conv3(bufA, bufB, nullptr, wbuf, rb_w1 + i*12288, rb_b1 + i*64,
                   3+2*i, 44-2*i, l0, hq, pb, tid);
        pred_conv3(bufB, bufA, bufA,    wbuf, rb_w2 + i*12288, rb_b2 + i*64,
                   4+2*i, 43-2*i, l0, hq, pb, tid);
    }
    __syncthreads();
    #pragma unroll
    for (int m = 0; m < 2; m++)
    #pragma unroll
    for (int j = 0; j < 3; j++){
        int p = pb + j;
        if (p >= 8 && p <= 39){
            int l = l0 - 8 + p;
            int ch0 = hq*4 + 2*m;
            g_F0[(b*H_ + ch0    )*L_ + l] = bufA[ch0*52 + p + 2];
            g_F0[(b*H_ + ch0 + 1)*L_ + l] = bufA[(ch0+1)*52 + p + 2];
        }
    }
}

// ============================================================
// K5: kern conv GEMM (f32x2), tile 128(kc) x 64(n), double-
// buffered (R13 version). 2 tail block-rows -> bias conv g_BS.
// ============================================================
__global__ void __launch_bounds__(256)
k_kern_gemm(const float* __restrict__ A, const float* __restrict__ Ab,
            const float* __restrict__ Bw, const float* __restrict__ Bb){
    int kc0 = blockIdx.x * 128;
    bool is_bias = (kc0 >= KC_);
    int n0  = blockIdx.y * 64;
    int b   = n0 / L_;
    int l0w = n0 % L_;
    int tid = threadIdx.x;
    int warp = tid >> 5, lane = tid & 31;
    int ty = (warp << 1) | (lane >> 4);
    int tx = lane & 15;
    __shared__ __align__(16) float As[2][16][128];
    __shared__ __align__(16) float Xs[2][16][68];
    const float* F = &g_F0[b*H_*L_];
    const float* Arow_base = is_bias ? Bw : A;
    const float* bias_base = is_bias ? Bb : Ab;
    int row_off = is_bias ? (kc0 - KC_) : kc0;

    uint64_t acc[4][4];
    #pragma unroll
    for (int m = 0; m < 4; m++){
        uint64_t bp = pack2f(bias_base[row_off + ty*8 + 2*m],
                             bias_base[row_off + ty*8 + 2*m + 1]);
        #pragma unroll
        for (int j = 0; j < 4; j++) acc[m][j] = bp;
    }
    int arow = tid >> 1, ac0 = (tid & 1) * 8;
    int xrr = tid >> 4, xc0 = (tid & 15) * 4;
    const float* Aptr = &Arow_base[(row_off + arow)*192 + ac0];

    {
        float4 v0 = *(const float4*)(Aptr);
        float4 v1 = *(const float4*)(Aptr + 4);
        As[0][ac0+0][arow] = v0.x; As[0][ac0+1][arow] = v0.y;
        As[0][ac0+2][arow] = v0.z; As[0][ac0+3][arow] = v0.w;
        As[0][ac0+4][arow] = v1.x; As[0][ac0+5][arow] = v1.y;
        As[0][ac0+6][arow] = v1.z; As[0][ac0+7][arow] = v1.w;
        int hh = xrr/3, k = xrr%3;
        #pragma unroll
        for (int q = 0; q < 4; q++){
            int t = l0w + xc0 + q + k - 1;
            Xs[0][xrr][xc0+q] = (t >= 0 && t < L_) ? F[hh*L_ + t] : 0.f;
        }
    }
    __syncthreads();

    #pragma unroll 1
    for (int bk = 0; bk < 12; bk++){
        int cur = bk & 1, nxt = cur ^ 1;
        if (bk < 11){
            int r0 = (bk + 1)*16;
            float4 v0 = *(const float4*)(Aptr + r0);
            float4 v1 = *(const float4*)(Aptr + r0 + 4);
            As[nxt][ac0+0][arow] = v0.x; As[nxt][ac0+1][arow] = v0.y;
            As[nxt][ac0+2][arow] = v0.z; As[nxt][ac0+3][arow] = v0.w;
            As[nxt][ac0+4][arow] = v1.x; As[nxt][ac0+5][arow] = v1.y;
            As[nxt][ac0+6][arow] = v1.z; As[nxt][ac0+7][arow] = v1.w;
            int r = r0 + xrr;
            int hh = r/3, k = r%3;
            #pragma unroll
            for (int q = 0; q < 4; q++){
                int t = l0w + xc0 + q + k - 1;
                Xs[nxt][xrr][xc0+q] = (t >= 0 && t < L_) ? F[hh*L_ + t] : 0.f;
            }
        }
        #pragma unroll
        for (int kk = 0; kk < 16; kk++){
            ulonglong2 aA = *(const ulonglong2*)&As[cur][kk][ty*8];
            ulonglong2 aB = *(const ulonglong2*)&As[cur][kk][ty*8 + 4];
            uint64_t a2[4] = {aA.x, aA.y, aB.x, aB.y};
            float4 xv = *(const float4*)&Xs[cur][kk][tx*4];
            uint64_t xb[4] = {bcast2f(xv.x), bcast2f(xv.y), bcast2f(xv.z), bcast2f(xv.w)};
            #pragma unroll
            for (int j = 0; j < 4; j++)
                #pragma unroll
                for (int m = 0; m < 4; m++)
                    fma2(acc[m][j], a2[m], xb[j]);
        }
        __syncthreads();
    }
    if (!is_bias){
        #pragma unroll
        for (int j = 0; j < 4; j++){
            int n = n0 + tx*4 + j;
            #pragma unroll
            for (int m = 0; m < 4; m++){
                float2 p = unpack2f(acc[m][j]);
                *(float2*)&g_KT[n*KC_ + kc0 + ty*8 + 2*m] = p;
            }
        }
    } else {
        #pragma unroll
        for (int j = 0; j < 4; j++){
            int l = l0w + tx*4 + j;
            #pragma unroll
            for (int m = 0; m < 4; m++){
                float2 p = unpack2f(acc[m][j]);
                int bc = row_off + ty*8 + 2*m;
                g_BS[(b*256 + bc    )*L_ + l] = p.x;
                g_BS[(b*256 + bc + 1)*L_ + l] = p.y;
            }
        }
    }
}

// ============================================================
// K7+K8 FUSED (512 threads): lrelu -> dilated conv -> lrelu
// (smem sc) -> LVC + bias + gating + residual.
// 16 warps: warp&3 -> 8-channel group, warp>>2 -> 64-sample
// quarter; samples = sbase + 32m (m=0..1), lane-contiguous.
// ============================================================
#define FUSED_SMEM ((32*312 + 3072 + 32*264 + 6144)*4)
template<int D>
__global__ void __launch_bounds__(512)
k_fused(int layer, const float* __restrict__ w, const float* __restrict__ bias,
        float* __restrict__ outp){
    extern __shared__ float sm[];
    float* sx  = sm;                    // 32 x 312: lrelu(Hin) window
    float* ws  = sm + 32*312;           // [k][i][o] 3072
    float* sc  = ws + 3072;             // 32 x 264 (258 used): conv out
    float* ksh = sc + 32*264;           // [k][c][o] 6144
    int b = blockIdx.y, l = blockIdx.x;
    int tid = threadIdx.x;
    int lane = tid & 31, warp = tid >> 5;
    int tseg = l*HOP_;
    const float* Hin  = (layer & 1) ? g_C : g_H;
    float* Hout = outp ? outp : ((layer & 1) ? g_H : g_C);
    const float* Hb = &Hin[b*NCH*T_FULL];

    const int W2 = 258 + 2*D;
    for (int idx = tid; idx < NCH*W2; idx += 512){
        int c = idx / W2, q = idx % W2;
        int t = tseg - 1 - D + q;
        sx[c*312 + q] = (t >= 0 && t < T_FULL) ? lrelu(Hb[c*T_FULL + t]) : 0.f;
    }
    for (int idx = tid; idx < 3072; idx += 512){
        int o = idx / 96, rem = idx % 96;
        int i = rem / 3, k = rem % 3;
        ws[k*1024 + i*32 + o] = w[idx];
    }
    const float* KTb = &g_KT[(b*L_ + l)*KC_ + layer*6144];
    const float4* K4 = (const float4*)KTb;
    for (int i4 = tid; i4 < 1536; i4 += 512){
        float4 v = K4[i4];
        float vv[4] = {v.x, v.y, v.z, v.w};
        int base = i4*4;
        #pragma unroll
        for (int e = 0; e < 4; e++){
            int idx = base + e;
            int c = idx / 192, rem = idx % 192;
            int o = rem / 3, k = rem % 3;
            ksh[k*2048 + c*64 + o] = vv[e];
        }
    }
    __syncthreads();

    int o0    = (warp & 3) * 8;            // 8 channels per thread
    int sbase = (warp >> 2) * 64 + lane;   // samples sbase + 32m, m=0..1

    // --- dconv phase 1: p in [0,256) ---
    {
        uint64_t acc[4][2];
        #pragma unroll
        for (int cp = 0; cp < 4; cp++){
            uint64_t bp = pack2f(bias[o0 + 2*cp], bias[o0 + 2*cp + 1]);
            acc[cp][0] = bp; acc[cp][1] = bp;
        }
        for (int i = 0; i < NCH; i++){
            const float* xr = &sx[i*312 + sbase];
            #pragma unroll
            for (int k = 0; k < 3; k++){
                ulonglong2 wA = *(const ulonglong2*)&ws[k*1024 + i*32 + o0];
                ulonglong2 wB = *(const ulonglong2*)&ws[k*1024 + i*32 + o0 + 4];
                uint64_t wp[4] = {wA.x, wA.y, wB.x, wB.y};
                #pragma unroll
                for (int m = 0; m < 2; m++){
                    uint64_t xb = bcast2f(xr[32*m + k*D]);
                    fma2(acc[0][m], wp[0], xb);
                    fma2(acc[1][m], wp[1], xb);
                    fma2(acc[2][m], wp[2], xb);
                    fma2(acc[3][m], wp[3], xb);
                }
            }
        }
        #pragma unroll
        for (int cp = 0; cp < 4; cp++)
            #pragma unroll
            for (int m = 0; m < 2; m++){
                float2 u = unpack2f(acc[cp][m]);
                int p = sbase + 32*m;
                float v0 = lrelu(u.x), v1 = lrelu(u.y);
                if (l == 0 && p == 0){ v0 = 0.f; v1 = 0.f; }   // LVC zero-pad t=-1
                sc[(o0 + 2*cp    )*264 + p] = v0;
                sc[(o0 + 2*cp + 1)*264 + p] = v1;
            }
    }
    // --- dconv phase 2: p = 256, 257 (64 values, scalar) ---
    if (tid < 64){
        int ch = tid >> 1, p = 256 + (tid & 1);
        float acc = bias[ch];
        for (int i = 0; i < NCH; i++){
            #pragma unroll
            for (int k = 0; k < 3; k++)
                acc += ws[k*1024 + i*32 + ch] * sx[i*312 + p + k*D];
        }
        float v = lrelu(acc);
        if (l == L_ - 1 && p == 257) v = 0.f;         // LVC zero-pad t=T
        sc[ch*264 + p] = v;
    }
    __syncthreads();

    // --- LVC + gate + residual: 8 ch x 2 interleaved samples ---
    const float* Bb = &g_BS[(b*256 + layer*64)*L_];
    uint64_t accL[4][2], accH[4][2];
    #pragma unroll
    for (int cp = 0; cp < 4; cp++){
        uint64_t bl = pack2f(Bb[(o0 + 2*cp     )*L_ + l], Bb[(o0 + 2*cp + 1 )*L_ + l]);
        uint64_t bh = pack2f(Bb[(o0 + 2*cp + 32)*L_ + l], Bb[(o0 + 2*cp + 33)*L_ + l]);
        accL[cp][0] = bl; accL[cp][1] = bl;
        accH[cp][0] = bh; accH[cp][1] = bh;
    }
    for (int c = 0; c < NCH; c++){
        const float* xr = &sc[c*264 + sbase];
        #pragma unroll
        for (int k = 0; k < 3; k++){
            ulonglong2 wlA = *(const ulonglong2*)&ksh[k*2048 + c*64 + o0];
            ulonglong2 wlB = *(const ulonglong2*)&ksh[k*2048 + c*64 + o0 + 4];
            ulonglong2 whA = *(const ulonglong2*)&ksh[k*2048 + c*64 + o0 + 32];
            ulonglong2 whB = *(const ulonglong2*)&ksh[k*2048 + c*64 + o0 + 36];
            uint64_t wl[4] = {wlA.x, wlA.y, wlB.x, wlB.y};
            uint64_t wh[4] = {whA.x, whA.y, whB.x, whB.y};
            #pragma unroll
            for (int m = 0; m < 2; m++){
                uint64_t xb = bcast2f(xr[32*m + k]);
                fma2(accL[0][m], wl[0], xb);
                fma2(accL[1][m], wl[1], xb);
                fma2(accL[2][m], wl[2], xb);
                fma2(accL[3][m], wl[3], xb);
                fma2(accH[0][m], wh[0], xb);
                fma2(accH[1][m], wh[1], xb);
                fma2(accH[2][m], wh[2], xb);
                fma2(accH[3][m], wh[3], xb);
            }
        }
    }
    #pragma unroll
    for (int cp = 0; cp < 4; cp++)
        #pragma unroll
        for (int m = 0; m < 2; m++){
            int s = sbase + 32*m;
            int oc0 = o0 + 2*cp;
            float2 uL = unpack2f(accL[cp][m]);
            float2 uH = unpack2f(accH[cp][m]);
            float r0 = Hb[(oc0    )*T_FULL + tseg + s];
            float r1 = Hb[(oc0 + 1)*T_FULL + tseg + s];
            float sg0 = 1.f / (1.f + __expf(-uL.x));
            float sg1 = 1.f / (1.f + __expf(-uL.y));
            float th0 = tanhf(uH.x);
            float th1 = tanhf(uH.y);
            Hout[(b*NCH + oc0    )*T_FULL + tseg + s] = sg0*th0 + r0;
            Hout[(b*NCH + oc0 + 1)*T_FULL + tseg + s] = sg1*th1 + r1;
        }
}

// ============================================================
extern "C" void kernel_launch(void* const* d_in, const int* in_sizes, int n_in,
                              void* d_out, int out_size){
    const float* hidden  = (const float*)d_in[0];
    const float* spec    = (const float*)d_in[1];
    const float* convt_w = (const float*)d_in[2];
    const float* convt_b = (const float*)d_in[3];
    const float* kp_in_w = (const float*)d_in[4];
    const float* kp_in_b = (const float*)d_in[5];
    const float* rb_w1   = (const float*)d_in[6];
    const float* rb_b1   = (const float*)d_in[7];
    const float* rb_w2   = (const float*)d_in[8];
    const float* rb_b2   = (const float*)d_in[9];
    const float* kern_w  = (const float*)d_in[10];
    const float* kern_b  = (const float*)d_in[11];
    const float* bias_w  = (const float*)d_in[12];
    const float* bias_b  = (const float*)d_in[13];
    const float* lvc_w   = (const float*)d_in[14];
    const float* lvc_b   = (const float*)d_in[15];

    cudaFuncSetAttribute(k_pred, cudaFuncAttributeMaxDynamicSharedMemorySize, PRED_SMEM);
    cudaFuncSetAttribute(k_fused<1>,  cudaFuncAttributeMaxDynamicSharedMemorySize, FUSED_SMEM);
    cudaFuncSetAttribute(k_fused<3>,  cudaFuncAttributeMaxDynamicSharedMemorySize, FUSED_SMEM);
    cudaFuncSetAttribute(k_fused<9>,  cudaFuncAttributeMaxDynamicSharedMemorySize, FUSED_SMEM);
    cudaFuncSetAttribute(k_fused<27>, cudaFuncAttributeMaxDynamicSharedMemorySize, FUSED_SMEM);

    k_convT<<<dim3(256, B_), 256>>>(hidden, convt_w, convt_b);
    k_pred<<<dim3(B_, 8), 256, PRED_SMEM>>>(spec, kp_in_w, kp_in_b,
                                            rb_w1, rb_b1, rb_w2, rb_b2);
    // GEMM + fused bias conv
    k_kern_gemm<<<dim3(KC_/128 + 2, (B_*L_)/64), 256>>>(kern_w, kern_b, bias_w, bias_b);

    // four fused dconv+LVC layers (first one lands at ncu position)
    dim3 dg(L_, B_);
    k_fused<1> <<<dg, 512, FUSED_SMEM>>>(0, lvc_w,        lvc_b,      nullptr);
    k_fused<3> <<<dg, 512, FUSED_SMEM>>>(1, lvc_w + 3072, lvc_b + 32, nullptr);
    k_fused<9> <<<dg, 512, FUSED_SMEM>>>(2, lvc_w + 6144, lvc_b + 64, nullptr);
    k_fused<27><<<dg, 512, FUSED_SMEM>>>(3, lvc_w + 9216, lvc_b + 96, (float*)d_out);
}